// round 6
// baseline (speedup 1.0000x reference)
#include <cuda_runtime.h>
#include <cuda_bf16.h>

// PixCorr: mean over rows of per-row Pearson correlation between
// preds[n,:] and targets[n,:], each row D = 3*256*256 = 196608 fp32.
// Pure HBM-streaming problem (~402 MB read). One pass computing the 5
// sufficient statistics per row, then a tiny final mean kernel.

static constexpr int NROWS   = 256;
static constexpr int D_ELEMS = 3 * 256 * 256;       // 196608
static constexpr int D4      = D_ELEMS / 4;         // 49152 float4 per row
static constexpr int TPB     = 1024;

// Scratch for per-row correlations (no device allocation allowed).
__device__ float g_corr[NROWS];

__global__ void __launch_bounds__(TPB, 2)
pixcorr_row_kernel(const float* __restrict__ preds,
                   const float* __restrict__ targets)
{
    const int row = blockIdx.x;
    const float4* __restrict__ zp =
        reinterpret_cast<const float4*>(targets) + (size_t)row * D4;
    const float4* __restrict__ bp =
        reinterpret_cast<const float4*>(preds) + (size_t)row * D4;

    float sz = 0.f, sb = 0.f, szz = 0.f, sbb = 0.f, szb = 0.f;

    // 48 iterations per thread; unroll so ptxas front-batches the LDG.128s
    // (high MLP -> DRAM latency fully hidden).
    #pragma unroll 4
    for (int i = threadIdx.x; i < D4; i += TPB) {
        const float4 zv = zp[i];
        const float4 bv = bp[i];
        sz  += (zv.x + zv.y) + (zv.z + zv.w);
        sb  += (bv.x + bv.y) + (bv.z + bv.w);
        szz += zv.x * zv.x + zv.y * zv.y + zv.z * zv.z + zv.w * zv.w;
        sbb += bv.x * bv.x + bv.y * bv.y + bv.z * bv.z + bv.w * bv.w;
        szb += zv.x * bv.x + zv.y * bv.y + zv.z * bv.z + zv.w * bv.w;
    }

    // Warp-level reduction of all 5 accumulators.
    #pragma unroll
    for (int o = 16; o > 0; o >>= 1) {
        sz  += __shfl_xor_sync(0xffffffffu, sz,  o);
        sb  += __shfl_xor_sync(0xffffffffu, sb,  o);
        szz += __shfl_xor_sync(0xffffffffu, szz, o);
        sbb += __shfl_xor_sync(0xffffffffu, sbb, o);
        szb += __shfl_xor_sync(0xffffffffu, szb, o);
    }

    __shared__ float sm[5][32];
    const int warp = threadIdx.x >> 5;
    const int lane = threadIdx.x & 31;
    if (lane == 0) {
        sm[0][warp] = sz;
        sm[1][warp] = sb;
        sm[2][warp] = szz;
        sm[3][warp] = sbb;
        sm[4][warp] = szb;
    }
    __syncthreads();

    if (warp == 0) {
        sz  = sm[0][lane];
        sb  = sm[1][lane];
        szz = sm[2][lane];
        sbb = sm[3][lane];
        szb = sm[4][lane];
        #pragma unroll
        for (int o = 16; o > 0; o >>= 1) {
            sz  += __shfl_xor_sync(0xffffffffu, sz,  o);
            sb  += __shfl_xor_sync(0xffffffffu, sb,  o);
            szz += __shfl_xor_sync(0xffffffffu, szz, o);
            sbb += __shfl_xor_sync(0xffffffffu, sbb, o);
            szb += __shfl_xor_sync(0xffffffffu, szb, o);
        }
        if (lane == 0) {
            const float invD = 1.0f / (float)D_ELEMS;
            const float num  = szb - sz * sb * invD;
            const float vz   = fmaxf(szz - sz * sz * invD, 0.0f);
            const float vb   = fmaxf(sbb - sb * sb * invD, 0.0f);
            const float den  = sqrtf(vz) * sqrtf(vb) + 1e-6f;
            g_corr[row] = num / den;
        }
    }
}

__global__ void pixcorr_final_kernel(float* __restrict__ out)
{
    __shared__ float sm[8];
    float v = g_corr[threadIdx.x];           // 256 threads, one per row
    #pragma unroll
    for (int o = 16; o > 0; o >>= 1)
        v += __shfl_xor_sync(0xffffffffu, v, o);
    const int warp = threadIdx.x >> 5;
    const int lane = threadIdx.x & 31;
    if (lane == 0) sm[warp] = v;
    __syncthreads();
    if (threadIdx.x < 32) {
        v = (threadIdx.x < 8) ? sm[threadIdx.x] : 0.0f;
        #pragma unroll
        for (int o = 4; o > 0; o >>= 1)
            v += __shfl_xor_sync(0xffffffffu, v, o);
        if (threadIdx.x == 0)
            out[0] = v * (1.0f / (float)NROWS);
    }
}

extern "C" void kernel_launch(void* const* d_in, const int* in_sizes, int n_in,
                              void* d_out, int out_size)
{
    const float* preds   = (const float*)d_in[0];
    const float* targets = (const float*)d_in[1];
    float* out = (float*)d_out;

    pixcorr_row_kernel<<<NROWS, TPB>>>(preds, targets);
    pixcorr_final_kernel<<<1, NROWS>>>(out);
}

// round 7
// speedup vs baseline: 1.0060x; 1.0060x over previous
#include <cuda_runtime.h>
#include <cuda_bf16.h>

// PixCorr: mean over rows of per-row Pearson correlation between
// preds[n,:] and targets[n,:], each row D = 3*256*256 = 196608 fp32.
// Pure HBM-streaming (~402 MB read).
//
// Single fused kernel: 1024 blocks (4 chunks per row, 256 rows), each block
// computes 5 partial sufficient statistics for its chunk and writes them to
// a deterministic partials array. The last block to finish (threadfence +
// atomic counter) reduces the partials, computes per-row correlations, and
// writes the mean. Counter self-resets so the kernel is graph-replayable.

static constexpr int NROWS   = 256;
static constexpr int D_ELEMS = 3 * 256 * 256;        // 196608
static constexpr int D4      = D_ELEMS / 4;          // 49152 float4 per row
static constexpr int CHUNKS  = 4;                    // chunks per row
static constexpr int CHUNK4  = D4 / CHUNKS;          // 12288 float4 per chunk
static constexpr int GRID    = NROWS * CHUNKS;       // 1024 blocks
static constexpr int TPB     = 256;                  // 48 float4 iters/thread

// Scratch (device allocation is forbidden). Zero-initialized at module load;
// g_count is reset to 0 by the elected block at the end of every call.
__device__ float        g_part[GRID * 5];
__device__ unsigned int g_count;

__global__ void __launch_bounds__(TPB, 8)
pixcorr_fused_kernel(const float* __restrict__ preds,
                     const float* __restrict__ targets,
                     float* __restrict__ out)
{
    const int bid   = blockIdx.x;
    const int row   = bid >> 2;          // bid / CHUNKS
    const int chunk = bid & 3;           // bid % CHUNKS
    const size_t base = (size_t)row * D4 + (size_t)chunk * CHUNK4;

    const float4* __restrict__ zp = reinterpret_cast<const float4*>(targets) + base;
    const float4* __restrict__ bp = reinterpret_cast<const float4*>(preds)   + base;

    float sz = 0.f, sb = 0.f, szz = 0.f, sbb = 0.f, szb = 0.f;

    // 48 iterations per thread; unrolled so ptxas front-batches LDG.128s
    // (high MLP -> DRAM latency fully hidden).
    #pragma unroll 4
    for (int i = threadIdx.x; i < CHUNK4; i += TPB) {
        const float4 zv = zp[i];
        const float4 bv = bp[i];
        sz  += (zv.x + zv.y) + (zv.z + zv.w);
        sb  += (bv.x + bv.y) + (bv.z + bv.w);
        szz += zv.x * zv.x + zv.y * zv.y + zv.z * zv.z + zv.w * zv.w;
        sbb += bv.x * bv.x + bv.y * bv.y + bv.z * bv.z + bv.w * bv.w;
        szb += zv.x * bv.x + zv.y * bv.y + zv.z * bv.z + zv.w * bv.w;
    }

    // Warp-level reduction of all 5 accumulators.
    #pragma unroll
    for (int o = 16; o > 0; o >>= 1) {
        sz  += __shfl_xor_sync(0xffffffffu, sz,  o);
        sb  += __shfl_xor_sync(0xffffffffu, sb,  o);
        szz += __shfl_xor_sync(0xffffffffu, szz, o);
        sbb += __shfl_xor_sync(0xffffffffu, sbb, o);
        szb += __shfl_xor_sync(0xffffffffu, szb, o);
    }

    __shared__ float sm[5][8];
    const int warp = threadIdx.x >> 5;
    const int lane = threadIdx.x & 31;
    if (lane == 0) {
        sm[0][warp] = sz;  sm[1][warp] = sb;  sm[2][warp] = szz;
        sm[3][warp] = sbb; sm[4][warp] = szb;
    }
    __syncthreads();

    if (warp == 0 && lane < 8) {
        sz = sm[0][lane]; sb = sm[1][lane]; szz = sm[2][lane];
        sbb = sm[3][lane]; szb = sm[4][lane];
        #pragma unroll
        for (int o = 4; o > 0; o >>= 1) {
            sz  += __shfl_xor_sync(0x000000ffu, sz,  o);
            sb  += __shfl_xor_sync(0x000000ffu, sb,  o);
            szz += __shfl_xor_sync(0x000000ffu, szz, o);
            sbb += __shfl_xor_sync(0x000000ffu, sbb, o);
            szb += __shfl_xor_sync(0x000000ffu, szb, o);
        }
        if (lane == 0) {
            float* p = &g_part[bid * 5];
            p[0] = sz; p[1] = sb; p[2] = szz; p[3] = sbb; p[4] = szb;
        }
    }

    // ── Last-block-done election ──────────────────────────────────────────
    __shared__ bool is_last;
    __syncthreads();                     // ensure partial store has issued
    if (threadIdx.x == 0) {
        __threadfence();                 // make g_part write visible GPU-wide
        unsigned int old = atomicAdd(&g_count, 1u);
        is_last = (old == GRID - 1);
    }
    __syncthreads();
    if (!is_last) return;

    // ── Final stage: one block, 256 threads, one row each ─────────────────
    {
        const int r = threadIdx.x;       // TPB == NROWS
        float tsz = 0.f, tsb = 0.f, tszz = 0.f, tsbb = 0.f, tszb = 0.f;
        #pragma unroll
        for (int c = 0; c < CHUNKS; c++) {
            const float* p = &g_part[(r * CHUNKS + c) * 5];
            tsz += p[0]; tsb += p[1]; tszz += p[2]; tsbb += p[3]; tszb += p[4];
        }
        const float invD = 1.0f / (float)D_ELEMS;
        const float num  = tszb - tsz * tsb * invD;
        const float vz   = fmaxf(tszz - tsz * tsz * invD, 0.0f);
        const float vb   = fmaxf(tsbb - tsb * tsb * invD, 0.0f);
        const float den  = sqrtf(vz) * sqrtf(vb) + 1e-6f;
        float corr = num / den;

        // Mean over 256 correlations.
        #pragma unroll
        for (int o = 16; o > 0; o >>= 1)
            corr += __shfl_xor_sync(0xffffffffu, corr, o);
        __shared__ float cm[8];
        if (lane == 0) cm[warp] = corr;
        __syncthreads();
        if (threadIdx.x < 8) {
            float v = cm[threadIdx.x];
            #pragma unroll
            for (int o = 4; o > 0; o >>= 1)
                v += __shfl_xor_sync(0x000000ffu, v, o);
            if (threadIdx.x == 0) {
                out[0]  = v * (1.0f / (float)NROWS);
                g_count = 0;             // reset for next graph replay
            }
        }
    }
}

extern "C" void kernel_launch(void* const* d_in, const int* in_sizes, int n_in,
                              void* d_out, int out_size)
{
    const float* preds   = (const float*)d_in[0];
    const float* targets = (const float*)d_in[1];
    float* out = (float*)d_out;

    pixcorr_fused_kernel<<<GRID, TPB>>>(preds, targets, out);
}